// round 11
// baseline (speedup 1.0000x reference)
#include <cuda_runtime.h>
#include <cstdint>

// ---------------------------------------------------------------------------
// SkipGram negative-sampling: bit-exact JAX threefry gumbel top-k + dot products
// V=100000, D=512, B=1024, C=20, NEG=64
// Single fused main kernel: hash CTAs + positive-dot CTAs; last hash CTA per
// row runs that row's top-64 select + negative gather inline.
// ---------------------------------------------------------------------------

#define VV   100000
#define DD   512
#define BB   1024
#define CC   20
#define NEG  64
#define CAP  512
#define T0   (-5.5)        // prefilter: mean survivors ~e^5.55 ~ 257/row
#define HASH_CTAS 25       // 25*256*16 = 102400 >= VV

extern "C" __device__ float __nv_logf(float);

// -------- static scratch --------
__device__ float    d_logp[VV];
__device__ unsigned d_thresh[VV];
__device__ int      d_cnt[BB];
__device__ unsigned d_done[BB];
__device__ int      d_cand_v[BB * CAP];

// ---------------------------------------------------------------------------
// threefry2x32, key (0,42). Pipe balancing:
//  R_A round: add(IMAD,fma) + SHF(alu) + LOP3(alu)            = 1 fma / 2 alu
//  R_M round: add(IMAD,fma) + umulhi(fma) + mul.lo(fma)
//             + 3-input LOP3 (hi|lo)^x0 (alu)                 = 3 fma / 1 alu
// rot(x,r) == (umulhi(x,2^r) | x*2^r) exactly for 1<=r<=31.
// 8 of 20 rounds converted -> ~38 alu / ~38 fma ops per hash (balanced).
// `one` and multipliers are opaque kernel args (no const-folding to SHF).
// ---------------------------------------------------------------------------
#define R_A(r) { x0 = x0 * one + x1; x1 = __funnelshift_l(x1, x1, (r)) ^ x0; }
#define R_M(m) { x0 = x0 * one + x1;                                   \
                 unsigned hi_ = __umulhi(x1, (m));                     \
                 unsigned lo_ = x1 * (m);                              \
                 x1 = (hi_ | lo_) ^ x0; }

__device__ __forceinline__ unsigned tf_bits(unsigned ctr, unsigned one,
                                            uint4 M) {
    const unsigned ks1 = 42u, ks2 = 0x1BD11BF0u;   // 0x1BD11BDA ^ 42
    unsigned x0 = 0u;
    unsigned x1 = ctr + ks1;
    R_A(13) R_M(M.x) R_A(26) R_M(M.y)      // M.x = 1<<15, M.y = 1<<6
    x0 += ks1; x1 += ks2 + 1u;
    R_A(17) R_M(M.z) R_A(16) R_M(M.w)      // M.z = 1<<29, M.w = 1<<24
    x0 += ks2; x1 += 2u;
    R_A(13) R_M(M.x) R_A(26) R_M(M.y)
    x1 += ks1 + 3u;
    R_A(17) R_M(M.z) R_A(16) R_M(M.w)
    x0 += ks1; x1 += ks2 + 4u;
    R_A(13) R_A(15) R_A(26) R_A(6)         // last group stays SHF
    x0 += ks2; x1 += 5u;
    return x0 ^ x1;
}

// ---------------------------------------------------------------------------
// k0: per-word logp (exact f32, used by rescoring) + conservative integer
// prefilter threshold — MUFU path, margin 0.05 in score space plus an 8-ulp
// guard, both strictly enlarging the candidate set. Zeroes cnt + done.
// ---------------------------------------------------------------------------
__global__ __launch_bounds__(256) void k0_tables(const float* __restrict__ p) {
    int v = blockIdx.x * 256 + threadIdx.x;
    if (v < BB) { d_cnt[v] = 0; d_done[v] = 0u; }
    if (v >= VV) return;
    float pf = p[v];
    float lp = __nv_logf(pf);
    d_logp[v] = lp;
    float E = __expf(lp - (float)(T0 - 0.05));
    float ucrit = __expf(-E);
    int m = (int)floorf(ucrit * 8388608.0f) - 8;
    if (m < 0) m = 0;
    if (m > 8388607) m = 8388607;
    d_thresh[v] = ((unsigned)m) << 9;
}

// ---------------------------------------------------------------------------
// Row select + negative dots (executed by the LAST hash CTA of each row).
// ---------------------------------------------------------------------------
__device__ __noinline__ void row_select(int b, unsigned one, uint4 M,
                                        const int* __restrict__ center_ids,
                                        const float* __restrict__ Wc,
                                        const float* __restrict__ Wx,
                                        float* __restrict__ out,
                                        unsigned long long* key,
                                        float* ctr, int* negs) {
    int n = d_cnt[b];
    if (n > CAP) n = CAP;

    const size_t crow = (size_t)center_ids[b] * DD;
    for (int i = threadIdx.x; i < DD; i += 256) ctr[i] = Wc[crow + i];

    for (int s = threadIdx.x; s < CAP; s += 256) {
        unsigned long long kk = 0ull;
        if (s < n) {
            int v = d_cand_v[b * CAP + s];
            unsigned bits = tf_bits((unsigned)b * (unsigned)VV + (unsigned)v, one, M);
            unsigned m = bits >> 9;
            float f  = __fadd_rn(__uint_as_float(m | 0x3f800000u), -1.0f);
            float u  = __fadd_rn(f, 1.17549435e-38f);
            float e  = -__nv_logf(u);
            float g  = -__nv_logf(e);
            float sc = __fadd_rn(d_logp[v], g);
            unsigned sb = __float_as_uint(sc);
            sb = (sb & 0x80000000u) ? ~sb : (sb | 0x80000000u);
            kk = ((unsigned long long)sb << 32)
               | (unsigned long long)(0xFFFFFFFFu - (unsigned)v);
        }
        key[s] = kk;
    }
    __syncthreads();

    int sz = 64;
    while (sz < n) sz <<= 1;               // <= CAP

    for (int kk2 = 2; kk2 <= sz; kk2 <<= 1) {
        for (int j = kk2 >> 1; j > 0; j >>= 1) {
            for (int i = threadIdx.x; i < sz; i += 256) {
                int l = i ^ j;
                if (l > i) {
                    unsigned long long a = key[i], c = key[l];
                    bool up = ((i & kk2) == 0);
                    if ((a > c) == up) { key[i] = c; key[l] = a; }
                }
            }
            __syncthreads();
        }
    }

    if (threadIdx.x < NEG) {
        unsigned long long kk = key[sz - 1 - threadIdx.x];
        unsigned v = 0xFFFFFFFFu - (unsigned)(kk & 0xFFFFFFFFull);
        if (v >= VV) v = 0;
        negs[threadIdx.x] = (int)v;
    }
    __syncthreads();

    const int warp = threadIdx.x >> 5;
    const int lane = threadIdx.x & 31;
    const float4* ctr4 = (const float4*)ctr;
#pragma unroll
    for (int it = 0; it < 8; it++) {
        const int jn = it * 8 + warp;      // 0..63
        const float4* row4 = (const float4*)(Wx + (size_t)negs[jn] * DD);
        float acc = 0.0f;
#pragma unroll
        for (int t = 0; t < 4; t++) {
            float4 r = row4[lane + 32 * t];
            float4 c = ctr4[lane + 32 * t];
            acc += r.x * c.x + r.y * c.y + r.z * c.z + r.w * c.w;
        }
#pragma unroll
        for (int d2 = 16; d2 > 0; d2 >>= 1)
            acc += __shfl_down_sync(0xFFFFFFFFu, acc, d2);
        if (lane == 0) out[BB * CC + b * NEG + jn] = acc;
    }
}

// ---------------------------------------------------------------------------
// k1 (fully fused): grid (HASH_CTAS+3, B), __launch_bounds__(256, 6).
//  x <  HASH_CTAS : hash path — 16 v/thread, compute-and-discard threefry,
//                   per-survivor atomicAdd. Last CTA per row runs row_select.
//  x >= HASH_CTAS : positive-dot CTAs (memory-bound, overlap hashing).
// ---------------------------------------------------------------------------
__global__ __launch_bounds__(256, 6) void k1_fused(unsigned one, uint4 M,
                                                const int* __restrict__ center_ids,
                                                const int* __restrict__ context_ids,
                                                const float* __restrict__ Wc,
                                                const float* __restrict__ Wx,
                                                float* __restrict__ out) {
    __shared__ __align__(16) unsigned long long s_key[CAP];
    __shared__ __align__(16) float s_ctr[DD];
    __shared__ __align__(16) int   s_negs[NEG];
    __shared__ bool  s_last;

    const int b = blockIdx.y;

    if (blockIdx.x >= HASH_CTAS) {
        // ---- positive dots ----
        const int k = blockIdx.x - HASH_CTAS;           // 0..2
        const size_t crow = (size_t)center_ids[b] * DD;
        for (int i = threadIdx.x; i < DD; i += 256) s_ctr[i] = Wc[crow + i];
        __syncthreads();
        const int warp = threadIdx.x >> 5;
        const int lane = threadIdx.x & 31;
        const int j = k * 8 + warp;
        if (j < CC) {
            const float4* row4 = (const float4*)(Wc + (size_t)context_ids[b * CC + j] * DD);
            const float4* ctr4 = (const float4*)s_ctr;
            float acc = 0.0f;
#pragma unroll
            for (int t = 0; t < 4; t++) {
                float4 r = row4[lane + 32 * t];
                float4 c = ctr4[lane + 32 * t];
                acc += r.x * c.x + r.y * c.y + r.z * c.z + r.w * c.w;
            }
#pragma unroll
            for (int d2 = 16; d2 > 0; d2 >>= 1)
                acc += __shfl_down_sync(0xFFFFFFFFu, acc, d2);
            if (lane == 0) out[b * CC + j] = acc;
        }
        return;
    }

    // ---- hash path: 16 consecutive v per thread, 4-hash groups ----
    {
        const int tg = blockIdx.x * 256 + threadIdx.x;
        const int v0 = tg * 16;
        if (v0 < VV) {                      // VV % 16 == 0: per-thread uniform
            const unsigned base = (unsigned)b * (unsigned)VV + (unsigned)v0;
#pragma unroll
            for (int q = 0; q < 4; q++) {
                const uint4 t = *(const uint4*)&d_thresh[v0 + 4 * q];
                unsigned bits;
                bits = tf_bits(base + (unsigned)(4 * q + 0), one, M);
                if (bits >= t.x) {
                    int pos = atomicAdd(&d_cnt[b], 1);
                    if (pos < CAP) d_cand_v[b * CAP + pos] = v0 + 4 * q + 0;
                }
                bits = tf_bits(base + (unsigned)(4 * q + 1), one, M);
                if (bits >= t.y) {
                    int pos = atomicAdd(&d_cnt[b], 1);
                    if (pos < CAP) d_cand_v[b * CAP + pos] = v0 + 4 * q + 1;
                }
                bits = tf_bits(base + (unsigned)(4 * q + 2), one, M);
                if (bits >= t.z) {
                    int pos = atomicAdd(&d_cnt[b], 1);
                    if (pos < CAP) d_cand_v[b * CAP + pos] = v0 + 4 * q + 2;
                }
                bits = tf_bits(base + (unsigned)(4 * q + 3), one, M);
                if (bits >= t.w) {
                    int pos = atomicAdd(&d_cnt[b], 1);
                    if (pos < CAP) d_cand_v[b * CAP + pos] = v0 + 4 * q + 3;
                }
            }
        }
    }

    // ---- last-CTA-done handoff (threadFenceReduction pattern) ----
    __threadfence();
    __syncthreads();
    if (threadIdx.x == 0) {
        unsigned old = atomicAdd(&d_done[b], 1u);
        s_last = (old == (unsigned)(HASH_CTAS - 1));
    }
    __syncthreads();
    if (!s_last) return;
    __threadfence();

    row_select(b, one, M, center_ids, Wc, Wx, out, s_key, s_ctr, s_negs);
}

// ---------------------------------------------------------------------------
extern "C" void kernel_launch(void* const* d_in, const int* in_sizes, int n_in,
                              void* d_out, int out_size) {
    const int*   center_ids  = (const int*)d_in[0];
    const int*   context_ids = (const int*)d_in[1];
    const float* W_center    = (const float*)d_in[2];
    const float* W_context   = (const float*)d_in[3];
    const float* sample_prob = (const float*)d_in[4];
    float* out = (float*)d_out;

    k0_tables<<<(VV + 255) / 256, 256>>>(sample_prob);

    uint4 M = make_uint4(1u << 15, 1u << 6, 1u << 29, 1u << 24);
    dim3 g1(HASH_CTAS + 3, BB);   // 25 hash CTAs + 3 positive-dot CTAs per row
    k1_fused<<<g1, 256>>>(1u, M, center_ids, context_ids, W_center, W_context, out);
}

// round 12
// speedup vs baseline: 1.1528x; 1.1528x over previous
#include <cuda_runtime.h>
#include <cstdint>

// ---------------------------------------------------------------------------
// SkipGram negative-sampling: bit-exact JAX threefry gumbel top-k + dot products
// V=100000, D=512, B=1024, C=20, NEG=64
// ---------------------------------------------------------------------------

#define VV   100000
#define DD   512
#define BB   1024
#define CC   20
#define NEG  64
#define CAP  384
#define T0   (-5.0)        // prefilter: mean survivors ~e^5.05 ~ 156/row
#define HASH_CTAS 25       // 25*256*16 = 102400 >= VV

extern "C" __device__ float __nv_logf(float);

// -------- static scratch --------
__device__ float    d_logp[VV];
__device__ unsigned d_thresh[VV];
__device__ int      d_cnt[BB];
__device__ int      d_cand_v[BB * CAP];

// ---------------------------------------------------------------------------
// threefry2x32, key (0,42). Round add forced to IMAD (fma pipe) via opaque
// `one`; alu pipe carries exactly 20 SHF + 20 LOP3 (measured floor).
// ---------------------------------------------------------------------------
#define TFR(r) { x0 = x0 * one + x1; x1 = __funnelshift_l(x1, x1, (r)) ^ x0; }

__device__ __forceinline__ unsigned tf_bits(unsigned ctr, unsigned one) {
    const unsigned ks1 = 42u, ks2 = 0x1BD11BF0u;   // 0x1BD11BDA ^ 42
    unsigned x0 = 0u;
    unsigned x1 = ctr + ks1;
    TFR(13) TFR(15) TFR(26) TFR(6)
    x0 += ks1; x1 += ks2 + 1u;
    TFR(17) TFR(29) TFR(16) TFR(24)
    x0 += ks2; x1 += 2u;
    TFR(13) TFR(15) TFR(26) TFR(6)
    x1 += ks1 + 3u;
    TFR(17) TFR(29) TFR(16) TFR(24)
    x0 += ks1; x1 += ks2 + 4u;
    TFR(13) TFR(15) TFR(26) TFR(6)
    x0 += ks2; x1 += 5u;
    return x0 ^ x1;
}

// ---------------------------------------------------------------------------
// k0: per-word logp (exact f32, used by rescoring) + conservative integer
// prefilter threshold — MUFU path, margin 0.05 in score space plus an 8-ulp
// guard, both strictly enlarging the candidate set. Zeroes cnt.
// ---------------------------------------------------------------------------
__global__ __launch_bounds__(256) void k0_tables(const float* __restrict__ p) {
    int v = blockIdx.x * 256 + threadIdx.x;
    if (v < BB) d_cnt[v] = 0;
    if (v >= VV) return;
    float pf = p[v];
    float lp = __nv_logf(pf);
    d_logp[v] = lp;
    float E = __expf(lp - (float)(T0 - 0.05));
    float ucrit = __expf(-E);
    int m = (int)floorf(ucrit * 8388608.0f) - 8;
    if (m < 0) m = 0;
    if (m > 8388607) m = 8388607;
    d_thresh[v] = ((unsigned)m) << 9;
}

// ---------------------------------------------------------------------------
// k1 (hash + positive dots): grid (HASH_CTAS+3, B), launch_bounds(256,6).
//  x <  HASH_CTAS : hash path — 16 v/thread in 4-hash groups, compute-and-
//                   discard threefry, per-survivor atomicAdd (~0.4/warp).
//  x >= HASH_CTAS : positive-dot CTAs (memory-bound, overlap hashing).
// ---------------------------------------------------------------------------
__global__ __launch_bounds__(256, 6) void k1_fused(unsigned one,
                                                const int* __restrict__ center_ids,
                                                const int* __restrict__ context_ids,
                                                const float* __restrict__ Wc,
                                                float* __restrict__ out) {
    const int b = blockIdx.y;

    if (blockIdx.x >= HASH_CTAS) {
        // ---- positive dots ----
        __shared__ __align__(16) float s_ctr[DD];
        const int k = blockIdx.x - HASH_CTAS;           // 0..2
        const size_t crow = (size_t)center_ids[b] * DD;
        for (int i = threadIdx.x; i < DD; i += 256) s_ctr[i] = Wc[crow + i];
        __syncthreads();
        const int warp = threadIdx.x >> 5;
        const int lane = threadIdx.x & 31;
        const int j = k * 8 + warp;
        if (j < CC) {
            const float4* row4 = (const float4*)(Wc + (size_t)context_ids[b * CC + j] * DD);
            const float4* ctr4 = (const float4*)s_ctr;
            float acc = 0.0f;
#pragma unroll
            for (int t = 0; t < 4; t++) {
                float4 r = row4[lane + 32 * t];
                float4 c = ctr4[lane + 32 * t];
                acc += r.x * c.x + r.y * c.y + r.z * c.z + r.w * c.w;
            }
#pragma unroll
            for (int d2 = 16; d2 > 0; d2 >>= 1)
                acc += __shfl_down_sync(0xFFFFFFFFu, acc, d2);
            if (lane == 0) out[b * CC + j] = acc;
        }
        return;
    }

    // ---- hash path: 16 consecutive v per thread, 4-hash groups ----
    const int tg = blockIdx.x * 256 + threadIdx.x;
    const int v0 = tg * 16;
    if (v0 >= VV) return;                   // VV % 16 == 0: per-thread uniform

    const unsigned base = (unsigned)b * (unsigned)VV + (unsigned)v0;
#pragma unroll
    for (int q = 0; q < 4; q++) {
        const uint4 t = *(const uint4*)&d_thresh[v0 + 4 * q];
        unsigned bits;
        bits = tf_bits(base + (unsigned)(4 * q + 0), one);
        if (bits >= t.x) {
            int pos = atomicAdd(&d_cnt[b], 1);
            if (pos < CAP) d_cand_v[b * CAP + pos] = v0 + 4 * q + 0;
        }
        bits = tf_bits(base + (unsigned)(4 * q + 1), one);
        if (bits >= t.y) {
            int pos = atomicAdd(&d_cnt[b], 1);
            if (pos < CAP) d_cand_v[b * CAP + pos] = v0 + 4 * q + 1;
        }
        bits = tf_bits(base + (unsigned)(4 * q + 2), one);
        if (bits >= t.z) {
            int pos = atomicAdd(&d_cnt[b], 1);
            if (pos < CAP) d_cand_v[b * CAP + pos] = v0 + 4 * q + 2;
        }
        bits = tf_bits(base + (unsigned)(4 * q + 3), one);
        if (bits >= t.w) {
            int pos = atomicAdd(&d_cnt[b], 1);
            if (pos < CAP) d_cand_v[b * CAP + pos] = v0 + 4 * q + 3;
        }
    }
}

// ---------------------------------------------------------------------------
// k2 (fused select + negative dots): one CTA per b.
//  1. recompute hash per candidate, exact reference-f32 rescoring
//  2. bitonic top-64 over padded size sz (usually 256 now)
//     key = ordered(score)<<32 | ~v: score desc, index asc (XLA tie-break)
//  3. 8 warps stream the 64 negative rows of W_context, dot with center.
// ---------------------------------------------------------------------------
__global__ __launch_bounds__(256) void k2_fused(unsigned one,
                                                const int* __restrict__ center_ids,
                                                const float* __restrict__ Wc,
                                                const float* __restrict__ Wx,
                                                float* __restrict__ out) {
    __shared__ __align__(16) unsigned long long key[CAP < 512 ? 512 : CAP];
    __shared__ __align__(16) float ctr[DD];
    __shared__ __align__(16) int   negs[NEG];
    const int b = blockIdx.x;
    int n = d_cnt[b];
    if (n > CAP) n = CAP;

    int sz = 64;
    while (sz < n) sz <<= 1;               // usually 256

    // center row -> smem (overlaps with candidate rescoring)
    const size_t crow = (size_t)center_ids[b] * DD;
    for (int i = threadIdx.x; i < DD; i += 256) ctr[i] = Wc[crow + i];

    for (int s = threadIdx.x; s < sz; s += 256) {
        unsigned long long kk = 0ull;
        if (s < n) {
            int v = d_cand_v[b * CAP + s];
            unsigned bits = tf_bits((unsigned)b * (unsigned)VV + (unsigned)v, one);
            unsigned m = bits >> 9;
            float f  = __fadd_rn(__uint_as_float(m | 0x3f800000u), -1.0f);
            float u  = __fadd_rn(f, 1.17549435e-38f);
            float e  = -__nv_logf(u);
            float g  = -__nv_logf(e);
            float sc = __fadd_rn(d_logp[v], g);
            unsigned sb = __float_as_uint(sc);
            sb = (sb & 0x80000000u) ? ~sb : (sb | 0x80000000u);
            kk = ((unsigned long long)sb << 32)
               | (unsigned long long)(0xFFFFFFFFu - (unsigned)v);
        }
        key[s] = kk;
    }
    __syncthreads();

    for (int kk2 = 2; kk2 <= sz; kk2 <<= 1) {
        for (int j = kk2 >> 1; j > 0; j >>= 1) {
            for (int i = threadIdx.x; i < sz; i += 256) {
                int l = i ^ j;
                if (l > i) {
                    unsigned long long a = key[i], c = key[l];
                    bool up = ((i & kk2) == 0);
                    if ((a > c) == up) { key[i] = c; key[l] = a; }
                }
            }
            __syncthreads();
        }
    }

    if (threadIdx.x < NEG) {
        unsigned long long kk = key[sz - 1 - threadIdx.x];
        unsigned v = 0xFFFFFFFFu - (unsigned)(kk & 0xFFFFFFFFull);
        if (v >= VV) v = 0;
        negs[threadIdx.x] = (int)v;
    }
    __syncthreads();

    // ---- negative dots: 8 warps x 8 rows each ----
    const int warp = threadIdx.x >> 5;
    const int lane = threadIdx.x & 31;
    const float4* ctr4 = (const float4*)ctr;
#pragma unroll
    for (int it = 0; it < 8; it++) {
        const int jn = it * 8 + warp;      // 0..63
        const float4* row4 = (const float4*)(Wx + (size_t)negs[jn] * DD);
        float acc = 0.0f;
#pragma unroll
        for (int t = 0; t < 4; t++) {
            float4 r = row4[lane + 32 * t];
            float4 c = ctr4[lane + 32 * t];
            acc += r.x * c.x + r.y * c.y + r.z * c.z + r.w * c.w;
        }
#pragma unroll
        for (int d2 = 16; d2 > 0; d2 >>= 1)
            acc += __shfl_down_sync(0xFFFFFFFFu, acc, d2);
        if (lane == 0) out[BB * CC + b * NEG + jn] = acc;
    }
}

// ---------------------------------------------------------------------------
extern "C" void kernel_launch(void* const* d_in, const int* in_sizes, int n_in,
                              void* d_out, int out_size) {
    const int*   center_ids  = (const int*)d_in[0];
    const int*   context_ids = (const int*)d_in[1];
    const float* W_center    = (const float*)d_in[2];
    const float* W_context   = (const float*)d_in[3];
    const float* sample_prob = (const float*)d_in[4];
    float* out = (float*)d_out;

    k0_tables<<<(VV + 255) / 256, 256>>>(sample_prob);

    dim3 g1(HASH_CTAS + 3, BB);   // 25 hash CTAs + 3 positive-dot CTAs per row
    k1_fused<<<g1, 256>>>(1u, center_ids, context_ids, W_center, out);

    k2_fused<<<BB, 256>>>(1u, center_ids, W_center, W_context, out);
}